// round 1
// baseline (speedup 1.0000x reference)
#include <cuda_runtime.h>
#include <cuda_bf16.h>
#include <cstddef>

#define D_IN   96
#define D_OUT  256
#define MAXN   50000

// -------- scratch (device globals; no allocation allowed) --------
__device__ __align__(16) float g_agg[(size_t)MAXN * D_IN];    // 19.2 MB
__device__ __align__(16) float g_h[(size_t)MAXN * D_OUT];     // 51.2 MB
__device__ __align__(16) float g_scale[D_OUT];
__device__ __align__(16) float g_shift[D_OUT];

// -------- kernel 0: agg = eps * x --------
__global__ void init_agg_kernel(const float* __restrict__ x,
                                const float* __restrict__ eps, int n4) {
    int i = blockIdx.x * blockDim.x + threadIdx.x;
    if (i >= n4) return;
    float e = eps[0];
    float4 xv = reinterpret_cast<const float4*>(x)[i];
    reinterpret_cast<float4*>(g_agg)[i] =
        make_float4(e * xv.x, e * xv.y, e * xv.z, e * xv.w);
}

// -------- vectorized global reduction (sm_90+) --------
__device__ __forceinline__ void red_add_v4(float* addr, float4 v) {
    asm volatile("red.global.add.v4.f32 [%0], {%1, %2, %3, %4};"
                 :: "l"(addr), "f"(v.x), "f"(v.y), "f"(v.z), "f"(v.w)
                 : "memory");
}

// -------- kernel 1: edge scatter  agg[dst] += vals * x[src] --------
// one thread per (edge, 4-float chunk): 24 chunks cover D_IN=96
__global__ void edge_scatter_kernel(const float* __restrict__ x,
                                    const int* __restrict__ src,
                                    const int* __restrict__ dst,
                                    const float* __restrict__ vals, int E) {
    int idx = blockIdx.x * blockDim.x + threadIdx.x;
    int e = idx / 24;
    if (e >= E) return;
    int c = idx - e * 24;
    int s = __ldg(src + e);
    int d = __ldg(dst + e);
    float v = __ldg(vals + e);
    float4 xv = __ldg(reinterpret_cast<const float4*>(x + (size_t)s * D_IN) + c);
    red_add_v4(g_agg + (size_t)d * D_IN + c * 4,
               make_float4(v * xv.x, v * xv.y, v * xv.z, v * xv.w));
}

// -------- kernel 2: BN inference params --------
__global__ void bn_params_kernel(const float* __restrict__ gamma,
                                 const float* __restrict__ beta,
                                 const float* __restrict__ mean,
                                 const float* __restrict__ var) {
    int j = threadIdx.x;
    if (j < D_OUT) {
        float s = gamma[j] * rsqrtf(var[j] + 1e-3f);
        g_scale[j] = s;
        g_shift[j] = beta[j] - mean[j] * s;
    }
}

// -------- kernel 3/4: tiled SGEMM, optional BN+ReLU epilogue --------
#define BM 128
#define BN 128
#define BK 8

__global__ __launch_bounds__(256) void sgemm_kernel(
    const float* __restrict__ A, const float* __restrict__ B,
    float* __restrict__ C, int M, int N, int K,
    const float* __restrict__ scale, const float* __restrict__ shift,
    int relu)
{
    __shared__ float As[BK][BM];
    __shared__ float Bs[BK][BN];

    int tid  = threadIdx.x;
    int arow = tid >> 1;          // 0..127
    int acol = (tid & 1) << 2;    // 0 or 4
    int brow = tid >> 5;          // 0..7
    int bcol = (tid & 31) << 2;   // 0..124 step 4
    int tx = tid & 15;
    int ty = tid >> 4;
    int crow0 = blockIdx.y * BM;
    int ccol0 = blockIdx.x * BN;

    float acc[8][8];
    #pragma unroll
    for (int i = 0; i < 8; i++)
        #pragma unroll
        for (int j = 0; j < 8; j++) acc[i][j] = 0.f;

    const bool arow_ok = (crow0 + arow) < M;
    const float* Aptr = A + (size_t)(crow0 + arow) * K + acol;
    const float* Bptr = B + (size_t)brow * N + ccol0 + bcol;

    for (int k0 = 0; k0 < K; k0 += BK) {
        float4 a = arow_ok ? *reinterpret_cast<const float4*>(Aptr + k0)
                           : make_float4(0.f, 0.f, 0.f, 0.f);
        float4 b = *reinterpret_cast<const float4*>(Bptr + (size_t)k0 * N);
        __syncthreads();
        As[acol + 0][arow] = a.x;
        As[acol + 1][arow] = a.y;
        As[acol + 2][arow] = a.z;
        As[acol + 3][arow] = a.w;
        *reinterpret_cast<float4*>(&Bs[brow][bcol]) = b;
        __syncthreads();

        #pragma unroll
        for (int k = 0; k < BK; k++) {
            float4 a0 = *reinterpret_cast<const float4*>(&As[k][ty * 8]);
            float4 a1 = *reinterpret_cast<const float4*>(&As[k][ty * 8 + 4]);
            float4 b0 = *reinterpret_cast<const float4*>(&Bs[k][tx * 8]);
            float4 b1 = *reinterpret_cast<const float4*>(&Bs[k][tx * 8 + 4]);
            float av[8] = {a0.x, a0.y, a0.z, a0.w, a1.x, a1.y, a1.z, a1.w};
            float bv[8] = {b0.x, b0.y, b0.z, b0.w, b1.x, b1.y, b1.z, b1.w};
            #pragma unroll
            for (int i = 0; i < 8; i++)
                #pragma unroll
                for (int j = 0; j < 8; j++)
                    acc[i][j] = fmaf(av[i], bv[j], acc[i][j]);
        }
    }

    // epilogue
    float sc[8], sh[8];
    if (scale) {
        #pragma unroll
        for (int j = 0; j < 8; j++) {
            int col = ccol0 + tx * 8 + j;
            sc[j] = __ldg(scale + col);
            sh[j] = __ldg(shift + col);
        }
    }
    #pragma unroll
    for (int i = 0; i < 8; i++) {
        int row = crow0 + ty * 8 + i;
        if (row >= M) continue;
        float* Crow = C + (size_t)row * N + ccol0 + tx * 8;
        float v[8];
        #pragma unroll
        for (int j = 0; j < 8; j++) {
            float t = acc[i][j];
            if (scale) t = fmaf(t, sc[j], sh[j]);
            if (relu)  t = fmaxf(t, 0.f);
            v[j] = t;
        }
        *reinterpret_cast<float4*>(Crow)     = make_float4(v[0], v[1], v[2], v[3]);
        *reinterpret_cast<float4*>(Crow + 4) = make_float4(v[4], v[5], v[6], v[7]);
    }
}

extern "C" void kernel_launch(void* const* d_in, const int* in_sizes, int n_in,
                              void* d_out, int out_size) {
    const float* x        = (const float*)d_in[0];
    const int*   adj_src  = (const int*)  d_in[1];
    const int*   adj_dst  = (const int*)  d_in[2];
    const float* adj_vals = (const float*)d_in[3];
    const float* eps      = (const float*)d_in[4];
    const float* W0       = (const float*)d_in[5];
    const float* W1       = (const float*)d_in[6];
    const float* gamma    = (const float*)d_in[7];
    const float* beta     = (const float*)d_in[8];
    const float* bn_mean  = (const float*)d_in[9];
    const float* bn_var   = (const float*)d_in[10];
    float* out = (float*)d_out;

    int N = in_sizes[0] / D_IN;
    int E = in_sizes[1];

    void* p;
    cudaGetSymbolAddress(&p, g_agg);   float* agg   = (float*)p;
    cudaGetSymbolAddress(&p, g_h);     float* h     = (float*)p;
    cudaGetSymbolAddress(&p, g_scale); float* scale = (float*)p;
    cudaGetSymbolAddress(&p, g_shift); float* shift = (float*)p;

    // 0) agg = eps * x
    int n4 = N * (D_IN / 4);
    init_agg_kernel<<<(n4 + 255) / 256, 256>>>(x, eps, n4);

    // 1) scatter edges into agg with vectorized global reductions
    int work = E * (D_IN / 4);
    edge_scatter_kernel<<<(work + 255) / 256, 256>>>(x, adj_src, adj_dst, adj_vals, E);

    // 2) BN scale/shift
    bn_params_kernel<<<1, 256>>>(gamma, beta, bn_mean, bn_var);

    // 3) h = relu(BN(agg @ W0))
    dim3 grid1(D_OUT / BN, (N + BM - 1) / BM);
    sgemm_kernel<<<grid1, 256>>>(agg, W0, h, N, D_OUT, D_IN, scale, shift, 1);

    // 4) out = h @ W1
    sgemm_kernel<<<grid1, 256>>>(h, W1, out, N, D_OUT, D_OUT, nullptr, nullptr, 0);
}

// round 2
// speedup vs baseline: 1.5379x; 1.5379x over previous
#include <cuda_runtime.h>
#include <cuda_bf16.h>
#include <cstdint>
#include <cstddef>

#define D_IN   96
#define D_OUT  256
#define MAXN   50000

// -------- scratch (device globals; no allocation allowed) --------
__device__ __align__(16) float g_agg[(size_t)MAXN * D_IN];    // 19.2 MB
__device__ __align__(16) float g_h[(size_t)MAXN * D_OUT];     // 51.2 MB
__device__ __align__(16) float g_scale[D_OUT];
__device__ __align__(16) float g_shift[D_OUT];

// -------- kernel 0: agg = eps * x --------
__global__ void init_agg_kernel(const float* __restrict__ x,
                                const float* __restrict__ eps, int n4) {
    int i = blockIdx.x * blockDim.x + threadIdx.x;
    if (i >= n4) return;
    float e = eps[0];
    float4 xv = reinterpret_cast<const float4*>(x)[i];
    reinterpret_cast<float4*>(g_agg)[i] =
        make_float4(e * xv.x, e * xv.y, e * xv.z, e * xv.w);
}

// -------- vectorized global reduction (sm_90+) --------
__device__ __forceinline__ void red_add_v4(float* addr, float4 v) {
    asm volatile("red.global.add.v4.f32 [%0], {%1, %2, %3, %4};"
                 :: "l"(addr), "f"(v.x), "f"(v.y), "f"(v.z), "f"(v.w)
                 : "memory");
}

// -------- kernel 1: edge scatter  agg[dst] += vals * x[src] --------
__global__ void edge_scatter_kernel(const float* __restrict__ x,
                                    const int* __restrict__ src,
                                    const int* __restrict__ dst,
                                    const float* __restrict__ vals, int E) {
    int idx = blockIdx.x * blockDim.x + threadIdx.x;
    int e = idx / 24;
    if (e >= E) return;
    int c = idx - e * 24;
    int s = __ldg(src + e);
    int d = __ldg(dst + e);
    float v = __ldg(vals + e);
    float4 xv = __ldg(reinterpret_cast<const float4*>(x + (size_t)s * D_IN) + c);
    red_add_v4(g_agg + (size_t)d * D_IN + c * 4,
               make_float4(v * xv.x, v * xv.y, v * xv.z, v * xv.w));
}

// -------- kernel 2: BN inference params --------
__global__ void bn_params_kernel(const float* __restrict__ gamma,
                                 const float* __restrict__ beta,
                                 const float* __restrict__ mean,
                                 const float* __restrict__ var) {
    int j = threadIdx.x;
    if (j < D_OUT) {
        float s = gamma[j] * rsqrtf(var[j] + 1e-3f);
        g_scale[j] = s;
        g_shift[j] = beta[j] - mean[j] * s;
    }
}

// ======================= TF32 tensor-core GEMM =======================
// C[M,Nn] = A[M,K] @ B[K,Nn], optional per-column scale/shift + ReLU.
// Block tile 128x128, BK=16, 8 warps (2 M x 4 N), warp tile 64x32,
// mma.sync.m16n8k8.tf32, fp32 accumulate.
//
// SMEM column permutation: within each 8-wide k-group, column order is
// kk(k) = 2*(k&3) + ((k&4)>>2), so the (k, k+4) pair an mma fragment needs
// is adjacent -> every fragment load is a single LDS.64.

__device__ __forceinline__ uint32_t f2tf32(float f) {
    uint32_t u;
    asm("cvt.rna.tf32.f32 %0, %1;" : "=r"(u) : "f"(f));
    return u;
}

__device__ __forceinline__ void mma_tf32(float d[4], const uint32_t a[4],
                                         const uint32_t b[2], const float c[4]) {
    asm volatile(
        "mma.sync.aligned.m16n8k8.row.col.f32.tf32.tf32.f32 "
        "{%0,%1,%2,%3}, {%4,%5,%6,%7}, {%8,%9}, {%10,%11,%12,%13};"
        : "=f"(d[0]), "=f"(d[1]), "=f"(d[2]), "=f"(d[3])
        : "r"(a[0]), "r"(a[1]), "r"(a[2]), "r"(a[3]),
          "r"(b[0]), "r"(b[1]),
          "f"(c[0]), "f"(c[1]), "f"(c[2]), "f"(c[3]));
}

#define SAW 18   // smem stride in floats (pad 16 -> 18, keeps 8B align, spreads banks)

__global__ __launch_bounds__(256, 2) void mma_gemm_kernel(
    const float* __restrict__ A, const float* __restrict__ B,
    float* __restrict__ C, int M, int Nn, int K,
    const float* __restrict__ scale, const float* __restrict__ shift,
    int relu)
{
    __shared__ __align__(16) float As2[128 * SAW];
    __shared__ __align__(16) float Bs2[128 * SAW];

    const int tid  = threadIdx.x;
    const int lane = tid & 31;
    const int warp = tid >> 5;
    const int warpM = warp & 1;        // 0..1  -> 64 rows each
    const int warpN = warp >> 1;       // 0..3  -> 32 cols each
    const int gid  = lane >> 2;        // 0..7
    const int ctig = lane & 3;         // 0..3
    const int crow0 = blockIdx.y * 128;
    const int ccol0 = blockIdx.x * 128;

    float acc[4][4][4];
    #pragma unroll
    for (int mt = 0; mt < 4; mt++)
        #pragma unroll
        for (int nt = 0; nt < 4; nt++)
            #pragma unroll
            for (int i = 0; i < 4; i++) acc[mt][nt][i] = 0.f;

    // gmem load assignments (2 float4 each for A and B per thread)
    // A: id in [0,512): row=id>>2 (0..127), kb=(id&3)*4
    // B: id in [0,512): kr=id>>5 (0..15),  nb=(id&31)*4
    float4 va[2], vb[2];

    auto load_tiles = [&](int k0) {
        #pragma unroll
        for (int it = 0; it < 2; it++) {
            int id  = tid + it * 256;
            int row = id >> 2;
            int kb  = (id & 3) << 2;
            int grow = crow0 + row;
            va[it] = (grow < M)
                ? __ldg(reinterpret_cast<const float4*>(A + (size_t)grow * K + k0 + kb))
                : make_float4(0.f, 0.f, 0.f, 0.f);
            int kr = id >> 5;
            int nb = (id & 31) << 2;
            vb[it] = __ldg(reinterpret_cast<const float4*>(
                B + (size_t)(k0 + kr) * Nn + ccol0 + nb));
        }
    };

    auto store_tiles = [&]() {
        #pragma unroll
        for (int it = 0; it < 2; it++) {
            int id  = tid + it * 256;
            int row = id >> 2;
            int kb  = (id & 3) << 2;   // 0,4,8,12
            // col base in permuted layout: group (kb>>3)*8, start ((kb&4)>>2)
            int colb = ((kb >> 3) << 3) + ((kb & 4) >> 2);
            float* ap = &As2[row * SAW + colb];
            ap[0] = __uint_as_float(f2tf32(va[it].x));
            ap[2] = __uint_as_float(f2tf32(va[it].y));
            ap[4] = __uint_as_float(f2tf32(va[it].z));
            ap[6] = __uint_as_float(f2tf32(va[it].w));

            int kr = id >> 5;          // 0..15
            int nb = (id & 31) << 2;
            int cc = ((kr >> 3) << 3) + 2 * (kr & 3) + ((kr & 4) >> 2);
            Bs2[(nb + 0) * SAW + cc] = __uint_as_float(f2tf32(vb[it].x));
            Bs2[(nb + 1) * SAW + cc] = __uint_as_float(f2tf32(vb[it].y));
            Bs2[(nb + 2) * SAW + cc] = __uint_as_float(f2tf32(vb[it].z));
            Bs2[(nb + 3) * SAW + cc] = __uint_as_float(f2tf32(vb[it].w));
        }
    };

    load_tiles(0);

    for (int k0 = 0; k0 < K; k0 += 16) {
        __syncthreads();
        store_tiles();
        __syncthreads();
        if (k0 + 16 < K) load_tiles(k0 + 16);

        #pragma unroll
        for (int ks = 0; ks < 2; ks++) {
            uint32_t af[4][4];
            #pragma unroll
            for (int mt = 0; mt < 4; mt++) {
                int r = warpM * 64 + mt * 16 + gid;
                float2 x0 = *reinterpret_cast<const float2*>(
                    &As2[r * SAW + ks * 8 + 2 * ctig]);
                float2 x1 = *reinterpret_cast<const float2*>(
                    &As2[(r + 8) * SAW + ks * 8 + 2 * ctig]);
                af[mt][0] = __float_as_uint(x0.x);  // (r,   k)
                af[mt][1] = __float_as_uint(x1.x);  // (r+8, k)
                af[mt][2] = __float_as_uint(x0.y);  // (r,   k+4)
                af[mt][3] = __float_as_uint(x1.y);  // (r+8, k+4)
            }
            uint32_t bf[4][2];
            #pragma unroll
            for (int nt = 0; nt < 4; nt++) {
                int n = warpN * 32 + nt * 8 + gid;
                float2 y = *reinterpret_cast<const float2*>(
                    &Bs2[n * SAW + ks * 8 + 2 * ctig]);
                bf[nt][0] = __float_as_uint(y.x);   // (k,   n)
                bf[nt][1] = __float_as_uint(y.y);   // (k+4, n)
            }
            #pragma unroll
            for (int mt = 0; mt < 4; mt++)
                #pragma unroll
                for (int nt = 0; nt < 4; nt++)
                    mma_tf32(acc[mt][nt], af[mt], bf[nt], acc[mt][nt]);
        }
    }

    // -------- epilogue: optional BN + ReLU, then store --------
    #pragma unroll
    for (int nt = 0; nt < 4; nt++) {
        int col = ccol0 + warpN * 32 + nt * 8 + 2 * ctig;
        float sc0 = 1.f, sc1 = 1.f, sh0 = 0.f, sh1 = 0.f;
        if (scale) {
            sc0 = __ldg(scale + col);     sc1 = __ldg(scale + col + 1);
            sh0 = __ldg(shift + col);     sh1 = __ldg(shift + col + 1);
        }
        #pragma unroll
        for (int mt = 0; mt < 4; mt++) {
            int row = crow0 + warpM * 64 + mt * 16 + gid;
            float v0 = acc[mt][nt][0], v1 = acc[mt][nt][1];
            float v2 = acc[mt][nt][2], v3 = acc[mt][nt][3];
            if (scale) {
                v0 = fmaf(v0, sc0, sh0); v1 = fmaf(v1, sc1, sh1);
                v2 = fmaf(v2, sc0, sh0); v3 = fmaf(v3, sc1, sh1);
            }
            if (relu) {
                v0 = fmaxf(v0, 0.f); v1 = fmaxf(v1, 0.f);
                v2 = fmaxf(v2, 0.f); v3 = fmaxf(v3, 0.f);
            }
            if (row < M)
                *reinterpret_cast<float2*>(C + (size_t)row * Nn + col) =
                    make_float2(v0, v1);
            if (row + 8 < M)
                *reinterpret_cast<float2*>(C + (size_t)(row + 8) * Nn + col) =
                    make_float2(v2, v3);
        }
    }
}

extern "C" void kernel_launch(void* const* d_in, const int* in_sizes, int n_in,
                              void* d_out, int out_size) {
    const float* x        = (const float*)d_in[0];
    const int*   adj_src  = (const int*)  d_in[1];
    const int*   adj_dst  = (const int*)  d_in[2];
    const float* adj_vals = (const float*)d_in[3];
    const float* eps      = (const float*)d_in[4];
    const float* W0       = (const float*)d_in[5];
    const float* W1       = (const float*)d_in[6];
    const float* gamma    = (const float*)d_in[7];
    const float* beta     = (const float*)d_in[8];
    const float* bn_mean  = (const float*)d_in[9];
    const float* bn_var   = (const float*)d_in[10];
    float* out = (float*)d_out;

    int N = in_sizes[0] / D_IN;
    int E = in_sizes[1];

    void* p;
    cudaGetSymbolAddress(&p, g_agg);   float* agg   = (float*)p;
    cudaGetSymbolAddress(&p, g_h);     float* h     = (float*)p;
    cudaGetSymbolAddress(&p, g_scale); float* scale = (float*)p;
    cudaGetSymbolAddress(&p, g_shift); float* shift = (float*)p;

    // 0) agg = eps * x
    int n4 = N * (D_IN / 4);
    init_agg_kernel<<<(n4 + 255) / 256, 256>>>(x, eps, n4);

    // 1) scatter edges into agg (vectorized L2 reductions)
    int work = E * (D_IN / 4);
    edge_scatter_kernel<<<(work + 255) / 256, 256>>>(x, adj_src, adj_dst, adj_vals, E);

    // 2) BN scale/shift
    bn_params_kernel<<<1, 256>>>(gamma, beta, bn_mean, bn_var);

    // 3) h = relu(BN(agg @ W0))   [N,96]@[96,256]
    dim3 grid(D_OUT / 128, (N + 127) / 128);
    mma_gemm_kernel<<<grid, 256>>>(agg, W0, h, N, D_OUT, D_IN, scale, shift, 1);

    // 4) out = h @ W1             [N,256]@[256,256]
    mma_gemm_kernel<<<grid, 256>>>(h, W1, out, N, D_OUT, D_OUT, nullptr, nullptr, 0);
}

// round 3
// speedup vs baseline: 1.9842x; 1.2902x over previous
#include <cuda_runtime.h>
#include <cuda_bf16.h>
#include <cstdint>
#include <cstddef>

#define D_IN   96
#define D_OUT  256
#define MAXN   50000

// -------- scratch (device globals; no allocation allowed) --------
__device__ __align__(16) float g_agg[(size_t)MAXN * D_IN];    // 19.2 MB
__device__ __align__(16) float g_h[(size_t)MAXN * D_OUT];     // 51.2 MB
__device__ __align__(16) float g_scale[D_OUT];
__device__ __align__(16) float g_shift[D_OUT];

// -------- kernel 0: agg = eps * x --------
__global__ void init_agg_kernel(const float* __restrict__ x,
                                const float* __restrict__ eps, int n4) {
    int i = blockIdx.x * blockDim.x + threadIdx.x;
    if (i >= n4) return;
    float e = eps[0];
    float4 xv = reinterpret_cast<const float4*>(x)[i];
    reinterpret_cast<float4*>(g_agg)[i] =
        make_float4(e * xv.x, e * xv.y, e * xv.z, e * xv.w);
}

// -------- vectorized global reduction (sm_90+) --------
__device__ __forceinline__ void red_add_v4(float* addr, float4 v) {
    asm volatile("red.global.add.v4.f32 [%0], {%1, %2, %3, %4};"
                 :: "l"(addr), "f"(v.x), "f"(v.y), "f"(v.z), "f"(v.w)
                 : "memory");
}

// -------- kernel 1: edge scatter  agg[dst] += vals * x[src] --------
__global__ void edge_scatter_kernel(const float* __restrict__ x,
                                    const int* __restrict__ src,
                                    const int* __restrict__ dst,
                                    const float* __restrict__ vals, int E) {
    int idx = blockIdx.x * blockDim.x + threadIdx.x;
    int e = idx / 24;
    if (e >= E) return;
    int c = idx - e * 24;
    int s = __ldg(src + e);
    int d = __ldg(dst + e);
    float v = __ldg(vals + e);
    float4 xv = __ldg(reinterpret_cast<const float4*>(x + (size_t)s * D_IN) + c);
    red_add_v4(g_agg + (size_t)d * D_IN + c * 4,
               make_float4(v * xv.x, v * xv.y, v * xv.z, v * xv.w));
}

// -------- kernel 2: BN inference params --------
__global__ void bn_params_kernel(const float* __restrict__ gamma,
                                 const float* __restrict__ beta,
                                 const float* __restrict__ mean,
                                 const float* __restrict__ var) {
    int j = threadIdx.x;
    if (j < D_OUT) {
        float s = gamma[j] * rsqrtf(var[j] + 1e-3f);
        g_scale[j] = s;
        g_shift[j] = beta[j] - mean[j] * s;
    }
}

// ======================= TF32 tensor-core GEMM =======================
// C[M,Nn] = A[M,K] @ B[K,Nn], optional per-column scale/shift + ReLU.
// Block 128x128, BK=16, 4 warps each 64x64, double-buffered SMEM.
// SMEM tiles stored K-major [k][m/n], stride 136 (8 mod 32) so that
// fragment LDS.32 lanes map to banks 8*ctig + gid (conflict-free).
// A columns get a per-k-group rotation (m + 8*(k>>2)) & 127 so the
// 4-per-column scatter stores also hit 32 distinct banks.
// B stores are coalesced STS.128 (conflict-free by construction).

__device__ __forceinline__ uint32_t f2tf32(float f) {
    uint32_t u;
    asm("cvt.rna.tf32.f32 %0, %1;" : "=r"(u) : "f"(f));
    return u;
}
__device__ __forceinline__ float tf32f(float f) {
    return __uint_as_float(f2tf32(f));
}

__device__ __forceinline__ void mma_tf32(float d[4], const uint32_t a[4],
                                         const uint32_t b[2], const float c[4]) {
    asm volatile(
        "mma.sync.aligned.m16n8k8.row.col.f32.tf32.tf32.f32 "
        "{%0,%1,%2,%3}, {%4,%5,%6,%7}, {%8,%9}, {%10,%11,%12,%13};"
        : "=f"(d[0]), "=f"(d[1]), "=f"(d[2]), "=f"(d[3])
        : "r"(a[0]), "r"(a[1]), "r"(a[2]), "r"(a[3]),
          "r"(b[0]), "r"(b[1]),
          "f"(c[0]), "f"(c[1]), "f"(c[2]), "f"(c[3]));
}

#define SBW 136   // smem row stride in floats; 136 % 32 == 8

__global__ __launch_bounds__(128, 2) void mma_gemm_kernel(
    const float* __restrict__ A, const float* __restrict__ B,
    float* __restrict__ C, int M, int Nn, int K,
    const float* __restrict__ scale, const float* __restrict__ shift,
    int relu)
{
    __shared__ __align__(16) float As[2][16 * SBW];
    __shared__ __align__(16) float Bs[2][16 * SBW];

    const int tid  = threadIdx.x;
    const int lane = tid & 31;
    const int warp = tid >> 5;
    const int warpM = warp & 1;        // 64 rows each
    const int warpN = warp >> 1;       // 64 cols each
    const int gid  = lane >> 2;        // 0..7
    const int ctig = lane & 3;         // 0..3
    const int crow0 = blockIdx.y * 128;
    const int ccol0 = blockIdx.x * 128;

    float acc[4][8][4];
    #pragma unroll
    for (int mt = 0; mt < 4; mt++)
        #pragma unroll
        for (int nt = 0; nt < 8; nt++)
            #pragma unroll
            for (int i = 0; i < 4; i++) acc[mt][nt][i] = 0.f;

    // gmem staging: 4 float4 each for A and B per thread per k16 tile
    // A: id = tid + it*128: m = id>>2 (0..127), kb = (id&3)*4
    // B: kr = id>>5 (0..15), nb = (id&31)*4
    float4 va[4], vb[4];

    auto load_g = [&](int k0) {
        #pragma unroll
        for (int it = 0; it < 4; it++) {
            int id = tid + it * 128;
            int m  = id >> 2;
            int kb = (id & 3) << 2;
            int grow = crow0 + m;
            va[it] = (grow < M)
                ? __ldg(reinterpret_cast<const float4*>(A + (size_t)grow * K + k0 + kb))
                : make_float4(0.f, 0.f, 0.f, 0.f);
            int kr = id >> 5;
            int nb = (id & 31) << 2;
            vb[it] = __ldg(reinterpret_cast<const float4*>(
                B + (size_t)(k0 + kr) * Nn + ccol0 + nb));
        }
    };

    auto store_s = [&](int buf) {
        #pragma unroll
        for (int it = 0; it < 4; it++) {
            int id = tid + it * 128;
            int m  = id >> 2;
            int kb = (id & 3) << 2;
            int col = (m + (kb << 1)) & 127;   // m + 8*(kb>>2)
            float* ap = &As[buf][0];
            ap[(kb + 0) * SBW + col] = tf32f(va[it].x);
            ap[(kb + 1) * SBW + col] = tf32f(va[it].y);
            ap[(kb + 2) * SBW + col] = tf32f(va[it].z);
            ap[(kb + 3) * SBW + col] = tf32f(va[it].w);

            int kr = id >> 5;
            int nb = (id & 31) << 2;
            float4 t = make_float4(tf32f(vb[it].x), tf32f(vb[it].y),
                                   tf32f(vb[it].z), tf32f(vb[it].w));
            *reinterpret_cast<float4*>(&Bs[buf][kr * SBW + nb]) = t;
        }
    };

    load_g(0);
    store_s(0);
    __syncthreads();

    const int nsteps = K >> 4;
    for (int s = 0; s < nsteps; s++) {
        const bool more = (s + 1 < nsteps);
        if (more) load_g((s + 1) << 4);

        const int buf = s & 1;
        const float* as = &As[buf][0];
        const float* bs = &Bs[buf][0];

        #pragma unroll
        for (int ks = 0; ks < 2; ks++) {
            const int kA = ks * 8 + ctig;
            uint32_t af[4][4];
            #pragma unroll
            for (int mt = 0; mt < 4; mt++) {
                int m0 = warpM * 64 + mt * 16 + gid;
                int c0 = (m0 + 16 * ks) & 127;
                int c1 = (m0 + 8 + 16 * ks) & 127;
                int c2 = (m0 + 16 + 16 * ks) & 127;
                af[mt][0] = __float_as_uint(as[kA * SBW + c0]);        // (k,   m0)
                af[mt][1] = __float_as_uint(as[kA * SBW + c1]);        // (k,   m0+8)
                af[mt][2] = __float_as_uint(as[(kA + 4) * SBW + c1]);  // (k+4, m0)
                af[mt][3] = __float_as_uint(as[(kA + 4) * SBW + c2]);  // (k+4, m0+8)
            }
            uint32_t bf[8][2];
            #pragma unroll
            for (int nt = 0; nt < 8; nt++) {
                int n0 = warpN * 64 + nt * 8 + gid;
                bf[nt][0] = __float_as_uint(bs[kA * SBW + n0]);        // (k,   n)
                bf[nt][1] = __float_as_uint(bs[(kA + 4) * SBW + n0]);  // (k+4, n)
            }
            #pragma unroll
            for (int mt = 0; mt < 4; mt++)
                #pragma unroll
                for (int nt = 0; nt < 8; nt++)
                    mma_tf32(acc[mt][nt], af[mt], bf[nt], acc[mt][nt]);
        }

        if (more) {
            store_s((s + 1) & 1);
            __syncthreads();
        }
    }

    // -------- epilogue: optional BN + ReLU, then store --------
    #pragma unroll
    for (int nt = 0; nt < 8; nt++) {
        int col = ccol0 + warpN * 64 + nt * 8 + 2 * ctig;
        float sc0 = 1.f, sc1 = 1.f, sh0 = 0.f, sh1 = 0.f;
        if (scale) {
            sc0 = __ldg(scale + col);     sc1 = __ldg(scale + col + 1);
            sh0 = __ldg(shift + col);     sh1 = __ldg(shift + col + 1);
        }
        #pragma unroll
        for (int mt = 0; mt < 4; mt++) {
            int row = crow0 + warpM * 64 + mt * 16 + gid;
            float v0 = acc[mt][nt][0], v1 = acc[mt][nt][1];
            float v2 = acc[mt][nt][2], v3 = acc[mt][nt][3];
            if (scale) {
                v0 = fmaf(v0, sc0, sh0); v1 = fmaf(v1, sc1, sh1);
                v2 = fmaf(v2, sc0, sh0); v3 = fmaf(v3, sc1, sh1);
            }
            if (relu) {
                v0 = fmaxf(v0, 0.f); v1 = fmaxf(v1, 0.f);
                v2 = fmaxf(v2, 0.f); v3 = fmaxf(v3, 0.f);
            }
            if (row < M)
                *reinterpret_cast<float2*>(C + (size_t)row * Nn + col) =
                    make_float2(v0, v1);
            if (row + 8 < M)
                *reinterpret_cast<float2*>(C + (size_t)(row + 8) * Nn + col) =
                    make_float2(v2, v3);
        }
    }
}

extern "C" void kernel_launch(void* const* d_in, const int* in_sizes, int n_in,
                              void* d_out, int out_size) {
    const float* x        = (const float*)d_in[0];
    const int*   adj_src  = (const int*)  d_in[1];
    const int*   adj_dst  = (const int*)  d_in[2];
    const float* adj_vals = (const float*)d_in[3];
    const float* eps      = (const float*)d_in[4];
    const float* W0       = (const float*)d_in[5];
    const float* W1       = (const float*)d_in[6];
    const float* gamma    = (const float*)d_in[7];
    const float* beta     = (const float*)d_in[8];
    const float* bn_mean  = (const float*)d_in[9];
    const float* bn_var   = (const float*)d_in[10];
    float* out = (float*)d_out;

    int N = in_sizes[0] / D_IN;
    int E = in_sizes[1];

    void* p;
    cudaGetSymbolAddress(&p, g_agg);   float* agg   = (float*)p;
    cudaGetSymbolAddress(&p, g_h);     float* h     = (float*)p;
    cudaGetSymbolAddress(&p, g_scale); float* scale = (float*)p;
    cudaGetSymbolAddress(&p, g_shift); float* shift = (float*)p;

    // 0) agg = eps * x
    int n4 = N * (D_IN / 4);
    init_agg_kernel<<<(n4 + 255) / 256, 256>>>(x, eps, n4);

    // 1) scatter edges into agg (vectorized L2 reductions)
    int work = E * (D_IN / 4);
    edge_scatter_kernel<<<(work + 255) / 256, 256>>>(x, adj_src, adj_dst, adj_vals, E);

    // 2) BN scale/shift
    bn_params_kernel<<<1, 256>>>(gamma, beta, bn_mean, bn_var);

    // 3) h = relu(BN(agg @ W0))   [N,96]@[96,256]
    dim3 grid(D_OUT / 128, (N + 127) / 128);
    mma_gemm_kernel<<<grid, 128>>>(agg, W0, h, N, D_OUT, D_IN, scale, shift, 1);

    // 4) out = h @ W1             [N,256]@[256,256]
    mma_gemm_kernel<<<grid, 128>>>(h, W1, out, N, D_OUT, D_OUT, nullptr, nullptr, 0);
}